// round 8
// baseline (speedup 1.0000x reference)
#include <cuda_runtime.h>
#include <cuda_fp16.h>
#include <stdint.h>

// ---------------------------------------------------------------------------
// Problem constants
// ---------------------------------------------------------------------------
#define DIN        64
#define HID        256
#define ROWS_TOTAL (256 * 2048)            // 524288
#define WARP_M     16
#define NTHREADS   384
#define NWARPS_CTA (NTHREADS / 32)         // 12
#define GRID_SMS   148
#define NWARPS_TOT (GRID_SMS * NWARPS_CTA) // 1776
#define MIN_VAL    (-1e8f)

// fp8 scale factors (exactly representable powers of 2)
#define W1_SCALE   8.0f
#define W2_SCALE   16.0f

// ---------------------------------------------------------------------------
// Device globals: compaction state
// ---------------------------------------------------------------------------
__device__ int g_count;
__device__ int g_idx[ROWS_TOTAL];

// ---------------------------------------------------------------------------
// SMEM layout (bytes).
// W1S: 256 n-rows x 64 fp8, stride 80  (bank-conflict-free for fragment LDS)
// W2S: 256 n-rows x 256 fp8, stride 272
// H1 : per-warp slab, 16 rows x 256 fp8, stride 272
// ---------------------------------------------------------------------------
#define W1_STRIDE 80
#define W2_STRIDE 272
#define H1_STRIDE 272
#define H1_SLAB   (WARP_M * H1_STRIDE)     // 4352

#define SM_W1S   0                                  // 256*80  = 20480
#define SM_W2S   (SM_W1S + HID * W1_STRIDE)         // 256*272 = 69632
#define SM_H1    (SM_W2S + HID * W2_STRIDE)         // 12*4352 = 52224
#define SM_S     (SM_H1 + NWARPS_CTA * H1_SLAB)
#define SM_C     (SM_S + 1024)
#define SM_B2    (SM_C + 1024)
#define SM_W3    (SM_B2 + 1024)
#define SM_TOTAL (SM_W3 + 1024)

// ---------------------------------------------------------------------------
// Helpers
// ---------------------------------------------------------------------------
__device__ __forceinline__ uint32_t smem_u32(const void* p) {
    uint32_t a;
    asm("{ .reg .u64 t; cvta.to.shared.u64 t, %1; cvt.u32.u64 %0, t; }" : "=r"(a) : "l"(p));
    return a;
}

// pack two floats -> e4m3x2 (bits 0-7 = lo, 8-15 = hi); returned in low 16 bits
__device__ __forceinline__ uint32_t fp8x2(float lo, float hi) {
    unsigned short r;
    asm("cvt.rn.satfinite.e4m3x2.f32 %0, %1, %2;" : "=h"(r) : "f"(hi), "f"(lo));
    return (uint32_t)r;
}

// pack two 16-bit values into 4 ascending bytes
__device__ __forceinline__ uint32_t pack4(uint32_t lo16, uint32_t hi16) {
    return lo16 | (hi16 << 16);
}

__device__ __forceinline__ uint32_t lds32(uint32_t addr) {
    uint32_t v;
    asm volatile("ld.shared.b32 %0, [%1];" : "=r"(v) : "r"(addr));
    return v;
}

__device__ __forceinline__ void sts16(uint32_t addr, uint32_t v) {
    asm volatile("st.shared.b16 [%0], %1;" :: "r"(addr), "h"((unsigned short)v));
}

// fp8 MMA: D(16x8 f32) += A(16x32 e4m3) * B(32x8 e4m3)
__device__ __forceinline__ void mma_e4m3(float* c,
                                         uint32_t a0, uint32_t a1, uint32_t a2, uint32_t a3,
                                         uint32_t b0, uint32_t b1) {
    asm volatile("mma.sync.aligned.m16n8k32.row.col.f32.e4m3.e4m3.f32 "
                 "{%0,%1,%2,%3}, {%4,%5,%6,%7}, {%8,%9}, {%0,%1,%2,%3};"
                 : "+f"(c[0]), "+f"(c[1]), "+f"(c[2]), "+f"(c[3])
                 : "r"(a0), "r"(a1), "r"(a2), "r"(a3), "r"(b0), "r"(b1));
}

// ---------------------------------------------------------------------------
// Kernel 0: zero the compaction counter
// ---------------------------------------------------------------------------
__global__ void zero_kernel() {
    g_count = 0;
}

// ---------------------------------------------------------------------------
// Kernel 1: init output to MIN_VAL, build compacted index list (warp-agg atomics)
// ---------------------------------------------------------------------------
__global__ void prep_kernel(const int* __restrict__ mask, float* __restrict__ out) {
    int row  = blockIdx.x * blockDim.x + threadIdx.x;
    int lane = threadIdx.x & 31;
    out[row] = MIN_VAL;
    bool v = (mask[row] != 0);
    uint32_t bal = __ballot_sync(0xFFFFFFFF, v);
    int base = 0;
    if (lane == 0 && bal) base = atomicAdd(&g_count, __popc(bal));
    base = __shfl_sync(0xFFFFFFFF, base, 0);
    if (v) g_idx[base + __popc(bal & ((1u << lane) - 1u))] = row;
}

// ---------------------------------------------------------------------------
// Main kernel: fp8 MMA, 16 rows per warp, fully warp-private inner loop
// ---------------------------------------------------------------------------
__global__ void __launch_bounds__(NTHREADS, 1) node_mlp_kernel(
    const float* __restrict__ obs,
    const float* __restrict__ W1, const float* __restrict__ b1,
    const float* __restrict__ gamma, const float* __restrict__ beta,
    const float* __restrict__ rmean, const float* __restrict__ rvar,
    const float* __restrict__ W2, const float* __restrict__ b2,
    const float* __restrict__ W3, const float* __restrict__ b3,
    float* __restrict__ out)
{
    extern __shared__ char smem[];
    const uint32_t sb = smem_u32(smem);
    const int tid  = threadIdx.x;
    const int wid  = tid >> 5;
    const int lane = tid & 31;

    uint8_t* w1s = (uint8_t*)(smem + SM_W1S);
    uint8_t* w2s = (uint8_t*)(smem + SM_W2S);

    // ---- one-time weight staging (f32 -> scaled e4m3) ----
    #pragma unroll 4
    for (int idx = tid; idx < DIN * HID; idx += NTHREADS) {
        int k = idx >> 8, n = idx & 255;           // W1[k][n]
        w1s[n * W1_STRIDE + k] = (uint8_t)(fp8x2(W1[idx] * W1_SCALE, 0.0f) & 0xFF);
    }
    #pragma unroll 4
    for (int idx = tid; idx < HID * HID; idx += NTHREADS) {
        int k = idx >> 8, n = idx & 255;           // W2[k][n]
        w2s[n * W2_STRIDE + k] = (uint8_t)(fp8x2(W2[idx] * W2_SCALE, 0.0f) & 0xFF);
    }
    for (int n = tid; n < HID; n += NTHREADS) {
        float s = gamma[n] * rsqrtf(rvar[n] + 1e-5f);
        ((float*)(smem + SM_S))[n]  = s * (1.0f / W1_SCALE);      // applied to 8x-scaled d1
        ((float*)(smem + SM_C))[n]  = (b1[n] - rmean[n]) * s + beta[n];
        ((float*)(smem + SM_B2))[n] = b2[n] * W2_SCALE;           // 16*b2
        ((float*)(smem + SM_W3))[n] = W3[n] * (1.0f / W2_SCALE);  // W3/16
    }
    const float b3v = __ldg(b3);
    __syncthreads();

    const float* Sv  = (const float*)(smem + SM_S);
    const float* Cv  = (const float*)(smem + SM_C);
    const float* B2v = (const float*)(smem + SM_B2);
    const float* W3v = (const float*)(smem + SM_W3);

    const int cnt    = g_count;
    const int ntiles = (cnt + WARP_M - 1) >> 4;

    const int g = lane >> 2;            // 0..7 (fragment row / B col group)
    const int q = lane & 3;             // 0..3 (k nibble / output col pair)
    const int t2 = q * 2;

    // per-lane smem address bases
    const uint32_t w1a  = sb + SM_W1S + (uint32_t)g * W1_STRIDE + (uint32_t)q * 4;
    const uint32_t w2a  = sb + SM_W2S + (uint32_t)g * W2_STRIDE + (uint32_t)q * 4;
    const uint32_t h1b  = sb + SM_H1 + (uint32_t)wid * H1_SLAB;
    const uint32_t h1aA = h1b + (uint32_t)g * H1_STRIDE + (uint32_t)q * 4;   // A reads
    const uint32_t h1sW = h1b + (uint32_t)g * H1_STRIDE + t2;                // stores row g

    const int gwid = blockIdx.x * NWARPS_CTA + wid;

    for (int wt = gwid; wt < ntiles; wt += NWARPS_TOT) {
        const int i0 = wt * WARP_M;

        // ---- gather X rows, convert f32 -> e4m3 A fragments in registers ----
        const int ri0 = g_idx[min(i0 + g, cnt - 1)];
        const int ri1 = g_idx[min(i0 + 8 + g, cnt - 1)];
        uint32_t ax[2][4];
        {
            const float4* r0p = (const float4*)(obs + (size_t)ri0 * DIN + q * 4);
            const float4* r1p = (const float4*)(obs + (size_t)ri1 * DIN + q * 4);
            #pragma unroll
            for (int s = 0; s < 2; s++) {
                float4 f;
                f = r0p[s * 8];        ax[s][0] = pack4(fp8x2(f.x, f.y), fp8x2(f.z, f.w));
                f = r1p[s * 8];        ax[s][1] = pack4(fp8x2(f.x, f.y), fp8x2(f.z, f.w));
                f = r0p[s * 8 + 4];    ax[s][2] = pack4(fp8x2(f.x, f.y), fp8x2(f.z, f.w));
                f = r1p[s * 8 + 4];    ax[s][3] = pack4(fp8x2(f.x, f.y), fp8x2(f.z, f.w));
            }
        }

        // ---- GEMM1 (16x256x64) + BN + ReLU -> h1 (e4m3) into warp smem slab ----
        #pragma unroll
        for (int cc = 0; cc < 4; cc++) {
            float c[8][4];
            #pragma unroll
            for (int j = 0; j < 8; j++) { c[j][0]=0.f; c[j][1]=0.f; c[j][2]=0.f; c[j][3]=0.f; }
            #pragma unroll
            for (int s = 0; s < 2; s++) {
                #pragma unroll
                for (int j = 0; j < 8; j++) {
                    uint32_t ba = w1a + (uint32_t)(cc * 8 + j) * (8 * W1_STRIDE) + s * 32;
                    uint32_t b0 = lds32(ba);
                    uint32_t b1 = lds32(ba + 16);
                    mma_e4m3(c[j], ax[s][0], ax[s][1], ax[s][2], ax[s][3], b0, b1);
                }
            }
            #pragma unroll
            for (int j = 0; j < 8; j++) {
                int nt = cc * 8 + j;
                int n  = nt * 8 + t2;
                float s0 = Sv[n], s1 = Sv[n+1], d0 = Cv[n], d1 = Cv[n+1];
                float v00 = fmaxf(fmaf(c[j][0], s0, d0), 0.0f);
                float v01 = fmaxf(fmaf(c[j][1], s1, d1), 0.0f);
                float v10 = fmaxf(fmaf(c[j][2], s0, d0), 0.0f);
                float v11 = fmaxf(fmaf(c[j][3], s1, d1), 0.0f);
                sts16(h1sW + nt * 8,                   fp8x2(v00, v01));
                sts16(h1sW + nt * 8 + 8 * H1_STRIDE,   fp8x2(v10, v11));
            }
        }
        __syncwarp();

        // ---- GEMM2 (16x256x256) + bias + ReLU + dot(W3) ----
        float y0 = 0.0f, y1 = 0.0f;
        for (int cc = 0; cc < 4; cc++) {
            float c[8][4];
            #pragma unroll
            for (int j = 0; j < 8; j++) { c[j][0]=0.f; c[j][1]=0.f; c[j][2]=0.f; c[j][3]=0.f; }
            #pragma unroll
            for (int s = 0; s < 8; s++) {
                uint32_t aa = h1aA + s * 32;
                uint32_t a0 = lds32(aa);
                uint32_t a1 = lds32(aa + 8 * H1_STRIDE);
                uint32_t a2 = lds32(aa + 16);
                uint32_t a3 = lds32(aa + 8 * H1_STRIDE + 16);
                #pragma unroll
                for (int j = 0; j < 8; j++) {
                    uint32_t ba = w2a + (uint32_t)(cc * 8 + j) * (8 * W2_STRIDE) + s * 32;
                    uint32_t b0 = lds32(ba);
                    uint32_t b1 = lds32(ba + 16);
                    mma_e4m3(c[j], a0, a1, a2, a3, b0, b1);
                }
            }
            #pragma unroll
            for (int j = 0; j < 8; j++) {
                int n = (cc * 8 + j) * 8 + t2;
                float bb0 = B2v[n], bb1 = B2v[n+1], w30 = W3v[n], w31 = W3v[n+1];
                y0 = fmaf(fmaxf(c[j][0] + bb0, 0.0f), w30, y0);
                y0 = fmaf(fmaxf(c[j][1] + bb1, 0.0f), w31, y0);
                y1 = fmaf(fmaxf(c[j][2] + bb0, 0.0f), w30, y1);
                y1 = fmaf(fmaxf(c[j][3] + bb1, 0.0f), w31, y1);
            }
        }

        // ---- reduce over 4 lanes per row group, scatter ----
        y0 += __shfl_xor_sync(0xFFFFFFFF, y0, 1);
        y0 += __shfl_xor_sync(0xFFFFFFFF, y0, 2);
        y1 += __shfl_xor_sync(0xFFFFFFFF, y1, 1);
        y1 += __shfl_xor_sync(0xFFFFFFFF, y1, 2);
        if (q == 0) {
            int i1 = i0 + g;
            int i2 = i0 + 8 + g;
            if (i1 < cnt) out[g_idx[i1]] = y0 + b3v;
            if (i2 < cnt) out[g_idx[i2]] = y1 + b3v;
        }
        __syncwarp();
    }
}

// ---------------------------------------------------------------------------
// Launch
// ---------------------------------------------------------------------------
extern "C" void kernel_launch(void* const* d_in, const int* in_sizes, int n_in,
                              void* d_out, int out_size)
{
    (void)in_sizes; (void)n_in; (void)out_size;
    cudaFuncSetAttribute(node_mlp_kernel,
                         cudaFuncAttributeMaxDynamicSharedMemorySize, SM_TOTAL);

    zero_kernel<<<1, 1>>>();
    prep_kernel<<<ROWS_TOTAL / 256, 256>>>((const int*)d_in[1], (float*)d_out);
    node_mlp_kernel<<<GRID_SMS, NTHREADS, SM_TOTAL>>>(
        (const float*)d_in[0],  // obs
        (const float*)d_in[2],  // W1
        (const float*)d_in[3],  // b1
        (const float*)d_in[4],  // gamma
        (const float*)d_in[5],  // beta
        (const float*)d_in[6],  // run_mean
        (const float*)d_in[7],  // run_var
        (const float*)d_in[8],  // W2
        (const float*)d_in[9],  // b2
        (const float*)d_in[10], // W3
        (const float*)d_in[11], // b3
        (float*)d_out);
}

// round 11
// speedup vs baseline: 1.0815x; 1.0815x over previous
#include <cuda_runtime.h>
#include <cuda_fp16.h>
#include <stdint.h>

// ---------------------------------------------------------------------------
// Problem constants
// ---------------------------------------------------------------------------
#define DIN        64
#define HID        256
#define ROWS_TOTAL (256 * 2048)            // 524288
#define WARP_M     16
#define NTHREADS   384
#define NWARPS_CTA (NTHREADS / 32)         // 12
#define GRID_SMS   148
#define NWARPS_TOT (GRID_SMS * NWARPS_CTA) // 1776
#define MIN_VAL    (-1e8f)

// ---------------------------------------------------------------------------
// Device globals: compaction state
// ---------------------------------------------------------------------------
__device__ int g_count;
__device__ int g_idx[ROWS_TOTAL];

// ---------------------------------------------------------------------------
// SMEM layout (bytes). Padded strides: odd multiples of 16B -> conflict-free
// ldmatrix row addressing.
// ---------------------------------------------------------------------------
#define XSTRIDE_H  72          // halfs per row (144B = 9*16B)
#define W2STRIDE_H 264         // halfs per row (528B = 33*16B)

#define SM_X      0                                         // 12 * 16*72*2 = 27648
#define SM_W1T    (SM_X + NWARPS_CTA * WARP_M * XSTRIDE_H * 2)
#define SM_W2T    (SM_W1T + HID * XSTRIDE_H * 2)            // + 36864
#define SM_SH     (SM_W2T + HID * W2STRIDE_H * 2)           // + 135168 ; 256 half
#define SM_CH     (SM_SH + 512)                             // 256 half
#define SM_B2     (SM_CH + 512)                             // 256 f32
#define SM_W3     (SM_B2 + 1024)                            // 256 f32
#define SM_TOTAL  (SM_W3 + 1024)

// ---------------------------------------------------------------------------
// Helpers
// ---------------------------------------------------------------------------
__device__ __forceinline__ uint32_t smem_u32(const void* p) {
    uint32_t a;
    asm("{ .reg .u64 t; cvta.to.shared.u64 t, %1; cvt.u32.u64 %0, t; }" : "=r"(a) : "l"(p));
    return a;
}

__device__ __forceinline__ uint32_t h2u(__half2 v) {
    return *reinterpret_cast<uint32_t*>(&v);
}
__device__ __forceinline__ __half2 u2h(uint32_t v) {
    return *reinterpret_cast<__half2*>(&v);
}

__device__ __forceinline__ void ldm4(uint32_t* r, uint32_t addr) {
    asm volatile("ldmatrix.sync.aligned.m8n8.x4.shared.b16 {%0,%1,%2,%3}, [%4];"
                 : "=r"(r[0]), "=r"(r[1]), "=r"(r[2]), "=r"(r[3]) : "r"(addr));
}

// f16-accumulate HMMA: D(16x8 f16) += A(16x16 f16) * B(16x8 f16)
__device__ __forceinline__ void mma_h(uint32_t& c0, uint32_t& c1,
                                      uint32_t a0, uint32_t a1, uint32_t a2, uint32_t a3,
                                      uint32_t b0, uint32_t b1) {
    asm volatile("mma.sync.aligned.m16n8k16.row.col.f16.f16.f16.f16 "
                 "{%0,%1}, {%2,%3,%4,%5}, {%6,%7}, {%0,%1};"
                 : "+r"(c0), "+r"(c1)
                 : "r"(a0), "r"(a1), "r"(a2), "r"(a3), "r"(b0), "r"(b1));
}

// ---------------------------------------------------------------------------
// Kernel 0: zero the compaction counter
// ---------------------------------------------------------------------------
__global__ void zero_kernel() {
    g_count = 0;
}

// ---------------------------------------------------------------------------
// Kernel 1: init output to MIN_VAL, build compacted index list (warp-agg atomics)
// ---------------------------------------------------------------------------
__global__ void prep_kernel(const int* __restrict__ mask, float* __restrict__ out) {
    int row  = blockIdx.x * blockDim.x + threadIdx.x;
    int lane = threadIdx.x & 31;
    out[row] = MIN_VAL;
    bool v = (mask[row] != 0);
    uint32_t bal = __ballot_sync(0xFFFFFFFF, v);
    int base = 0;
    if (lane == 0 && bal) base = atomicAdd(&g_count, __popc(bal));
    base = __shfl_sync(0xFFFFFFFF, base, 0);
    if (v) g_idx[base + __popc(bal & ((1u << lane) - 1u))] = row;
}

// ---------------------------------------------------------------------------
// Main kernel: f16-accumulate HMMA, h1 register-resident, 16 rows/warp
// ---------------------------------------------------------------------------
__global__ void __launch_bounds__(NTHREADS, 1) node_mlp_kernel(
    const float* __restrict__ obs,
    const float* __restrict__ W1, const float* __restrict__ b1,
    const float* __restrict__ gamma, const float* __restrict__ beta,
    const float* __restrict__ rmean, const float* __restrict__ rvar,
    const float* __restrict__ W2, const float* __restrict__ b2,
    const float* __restrict__ W3, const float* __restrict__ b3,
    float* __restrict__ out)
{
    extern __shared__ char smem[];
    const uint32_t sb = smem_u32(smem);
    const int tid  = threadIdx.x;
    const int wid  = tid >> 5;
    const int lane = tid & 31;

    __half* w1t = (__half*)(smem + SM_W1T);
    __half* w2t = (__half*)(smem + SM_W2T);

    // ---- one-time weight staging ----
    for (int idx = tid; idx < DIN * HID; idx += NTHREADS) {
        int k = idx >> 8, n = idx & 255;           // W1[k][n]
        w1t[n * XSTRIDE_H + k] = __float2half(W1[idx]);
    }
    for (int idx = tid; idx < HID * HID; idx += NTHREADS) {
        int k = idx >> 8, n = idx & 255;           // W2[k][n]
        w2t[n * W2STRIDE_H + k] = __float2half(W2[idx]);
    }
    for (int n = tid; n < HID; n += NTHREADS) {
        float s = gamma[n] * rsqrtf(rvar[n] + 1e-5f);
        ((__half*)(smem + SM_SH))[n] = __float2half(s);
        ((__half*)(smem + SM_CH))[n] = __float2half((b1[n] - rmean[n]) * s + beta[n]);
        ((float*)(smem + SM_B2))[n]  = b2[n];
        ((float*)(smem + SM_W3))[n]  = W3[n];
    }
    const float b3v = __ldg(b3);
    __syncthreads();

    const __half* Sh  = (const __half*)(smem + SM_SH);
    const __half* Ch  = (const __half*)(smem + SM_CH);
    const float*  B2v = (const float*)(smem + SM_B2);
    const float*  W3v = (const float*)(smem + SM_W3);

    const int cnt    = g_count;
    const int ntiles = (cnt + WARP_M - 1) >> 4;

    const uint32_t xbase = sb + SM_X + wid * (WARP_M * XSTRIDE_H * 2);
    const uint32_t lrow = (uint32_t)(lane & 15);
    const uint32_t lcol = (uint32_t)(lane >> 4) * 16;       // bytes
    const uint32_t a_addr  = xbase + lrow * (XSTRIDE_H * 2) + lcol;
    const uint32_t w1_addr = sb + SM_W1T + lrow * (XSTRIDE_H * 2) + lcol;
    const uint32_t w2_addr = sb + SM_W2T + lrow * (W2STRIDE_H * 2) + lcol;

    const int g  = lane >> 2;           // 0..7 (output row within 8-row group)
    const int t2 = (lane & 3) * 2;      // 0,2,4,6 (output col pair)
    const __half2 zero2 = __float2half2_rn(0.0f);

    const int gwid = blockIdx.x * NWARPS_CTA + wid;

    for (int wt = gwid; wt < ntiles; wt += NWARPS_TOT) {
        const int i0 = wt * WARP_M;

        // ---- gather X 16x64 f32 -> f16 into this warp's smem slab ----
        {
            const int r    = lane >> 1;          // 0..15
            const int hsel = lane & 1;
            const int gi   = min(i0 + r, cnt - 1);
            const int row  = g_idx[gi];
            const float4* src = (const float4*)(obs + (size_t)row * DIN + hsel * 32);
            uint32_t dstoff = (xbase - sb) + (uint32_t)r * (XSTRIDE_H * 2) + (uint32_t)hsel * 64;
            #pragma unroll
            for (int i = 0; i < 8; i++) {
                float4 v = src[i];
                uint2 pk;
                pk.x = h2u(__floats2half2_rn(v.x, v.y));
                pk.y = h2u(__floats2half2_rn(v.z, v.w));
                *(uint2*)(smem + dstoff + i * 8) = pk;
            }
        }
        __syncwarp();

        // ---- A fragments for GEMM1 (4 k-steps of 16) ----
        uint32_t a[4][4];
        #pragma unroll
        for (int kk = 0; kk < 4; kk++) ldm4(a[kk], a_addr + kk * 32);

        // ---- GEMM1 (16x256x64, f16 accum) + BN + ReLU -> h1 in registers ----
        // h1lo[t] = rows g,   cols 8t+t2..+1 ; h1hi[t] = rows g+8 (t = n-tile 0..31)
        uint32_t h1lo[32], h1hi[32];
        #pragma unroll
        for (int cc = 0; cc < 4; cc++) {
            uint32_t c0[8], c1[8];
            #pragma unroll
            for (int j = 0; j < 8; j++) { c0[j] = 0u; c1[j] = 0u; }
            #pragma unroll
            for (int kk = 0; kk < 4; kk++) {
                #pragma unroll
                for (int p = 0; p < 4; p++) {
                    uint32_t b[4];
                    ldm4(b, w1_addr + (uint32_t)(cc * 64 + 16 * p) * (XSTRIDE_H * 2) + kk * 32);
                    mma_h(c0[2*p],   c1[2*p],   a[kk][0], a[kk][1], a[kk][2], a[kk][3], b[0], b[2]);
                    mma_h(c0[2*p+1], c1[2*p+1], a[kk][0], a[kk][1], a[kk][2], a[kk][3], b[1], b[3]);
                }
            }
            #pragma unroll
            for (int j = 0; j < 8; j++) {
                int n = cc * 64 + 8 * j + t2;
                __half2 s2 = *(const __half2*)(Sh + n);
                __half2 d2 = *(const __half2*)(Ch + n);
                h1lo[cc*8 + j] = h2u(__hmax2(__hfma2(u2h(c0[j]), s2, d2), zero2));
                h1hi[cc*8 + j] = h2u(__hmax2(__hfma2(u2h(c1[j]), s2, d2), zero2));
            }
        }

        // ---- GEMM2 (16x256x256, f16 accum, A from registers) + bias+ReLU+dot ----
        float y0 = 0.0f, y1 = 0.0f;
        for (int cc = 0; cc < 4; cc++) {            // not unrolled (code size)
            uint32_t c0[8], c1[8];
            #pragma unroll
            for (int j = 0; j < 8; j++) { c0[j] = 0u; c1[j] = 0u; }
            uint32_t wbase = w2_addr + (uint32_t)(cc * 64) * (W2STRIDE_H * 2);
            #pragma unroll
            for (int kk = 0; kk < 16; kk++) {
                uint32_t a0 = h1lo[2*kk],   a1 = h1hi[2*kk];
                uint32_t a2 = h1lo[2*kk+1], a3 = h1hi[2*kk+1];
                #pragma unroll
                for (int p = 0; p < 4; p++) {
                    uint32_t b[4];
                    ldm4(b, wbase + (uint32_t)(16 * p) * (W2STRIDE_H * 2) + kk * 32);
                    mma_h(c0[2*p],   c1[2*p],   a0, a1, a2, a3, b[0], b[2]);
                    mma_h(c0[2*p+1], c1[2*p+1], a0, a1, a2, a3, b[1], b[3]);
                }
            }
            #pragma unroll
            for (int j = 0; j < 8; j++) {
                int n = cc * 64 + 8 * j + t2;
                float bb0 = B2v[n], bb1 = B2v[n+1], w30 = W3v[n], w31 = W3v[n+1];
                float2 f0 = __half22float2(u2h(c0[j]));
                float2 f1 = __half22float2(u2h(c1[j]));
                y0 = fmaf(fmaxf(f0.x + bb0, 0.0f), w30, y0);
                y0 = fmaf(fmaxf(f0.y + bb1, 0.0f), w31, y0);
                y1 = fmaf(fmaxf(f1.x + bb0, 0.0f), w30, y1);
                y1 = fmaf(fmaxf(f1.y + bb1, 0.0f), w31, y1);
            }
        }

        // ---- reduce over 4 lanes per row group, scatter ----
        y0 += __shfl_xor_sync(0xFFFFFFFF, y0, 1);
        y0 += __shfl_xor_sync(0xFFFFFFFF, y0, 2);
        y1 += __shfl_xor_sync(0xFFFFFFFF, y1, 1);
        y1 += __shfl_xor_sync(0xFFFFFFFF, y1, 2);
        if ((lane & 3) == 0) {
            int i1 = i0 + g;
            int i2 = i0 + 8 + g;
            if (i1 < cnt) out[g_idx[i1]] = y0 + b3v;
            if (i2 < cnt) out[g_idx[i2]] = y1 + b3v;
        }
        __syncwarp();
    }
}

// ---------------------------------------------------------------------------
// Launch
// ---------------------------------------------------------------------------
extern "C" void kernel_launch(void* const* d_in, const int* in_sizes, int n_in,
                              void* d_out, int out_size)
{
    (void)in_sizes; (void)n_in; (void)out_size;
    cudaFuncSetAttribute(node_mlp_kernel,
                         cudaFuncAttributeMaxDynamicSharedMemorySize, SM_TOTAL);

    zero_kernel<<<1, 1>>>();
    prep_kernel<<<ROWS_TOTAL / 256, 256>>>((const int*)d_in[1], (float*)d_out);
    node_mlp_kernel<<<GRID_SMS, NTHREADS, SM_TOTAL>>>(
        (const float*)d_in[0],  // obs
        (const float*)d_in[2],  // W1
        (const float*)d_in[3],  // b1
        (const float*)d_in[4],  // gamma
        (const float*)d_in[5],  // beta
        (const float*)d_in[6],  // run_mean
        (const float*)d_in[7],  // run_var
        (const float*)d_in[8],  // W2
        (const float*)d_in[9],  // b2
        (const float*)d_in[10], // W3
        (const float*)d_in[11], // b3
        (float*)d_out);
}